// round 1
// baseline (speedup 1.0000x reference)
#include <cuda_runtime.h>

#define Bn 4
#define Cn 128
#define Hn 96
#define Wn 96
#define HWn (Hn*Wn)
#define Rn (Cn*9)

// Scratch (no allocations allowed): est activations, offsets, materialized bilinear samples.
__device__ float g_est[Bn*256*HWn];                 // 37.7 MB
__device__ float g_off[Bn*18*HWn];                  // 2.65 MB
__device__ float g_val[(size_t)Bn*Rn*HWn];          // 170 MB

// ---------------------------------------------------------------------------
// Generic 3x3 conv, NCHW, pad=1, stride=1. Input may be a channel-concat of
// two tensors (in0 for c < ic_split, in1 for c >= ic_split; both have
// per-batch channel count == ic_split for in0 / (IC-ic_split) for in1 when
// split, or ic_split==IC for a single tensor).
// Tile: TILE x TILE spatial, OCT output channels per block, TPT x TPT pixels
// per thread, blockDim = (TILE/TPT, TILE/TPT) = (16,16) = 256 threads.
// ---------------------------------------------------------------------------
template<int IC, int OC, int OCT, int OCTP, int TILE, int TPT, int ICB, bool RELU>
__global__ void __launch_bounds__(256)
conv3x3_k(const float* __restrict__ in0, const float* __restrict__ in1, int ic_split,
          const float* __restrict__ wgt, const float* __restrict__ bias,
          float* __restrict__ out)
{
    constexpr int TD = TILE / TPT;        // threads per spatial dim (16)
    constexpr int TS = TILE + 2;          // haloed tile
    constexpr int SS = (TS | 1);          // odd row stride -> no 2-way row conflict

    __shared__ float s_in[ICB][TS][SS];
    __shared__ float s_w[ICB][9][OCTP];

    const int tx = threadIdx.x, ty = threadIdx.y;
    const int tid = ty * TD + tx;
    constexpr int nOC = OC / OCT;
    const int b   = blockIdx.z / nOC;
    const int oc0 = (blockIdx.z % nOC) * OCT;
    const int x0  = blockIdx.x * TILE;
    const int y0  = blockIdx.y * TILE;

    float acc[OCT][TPT][TPT];
    #pragma unroll
    for (int o = 0; o < OCT; o++)
        #pragma unroll
        for (int py = 0; py < TPT; py++)
            #pragma unroll
            for (int px = 0; px < TPT; px++)
                acc[o][py][px] = 0.f;

    const int ic1 = IC - ic_split;  // channels in in1 (0 if single tensor)

    for (int ic0c = 0; ic0c < IC; ic0c += ICB) {
        // ---- load haloed input chunk ----
        const int nIn = ICB * TS * TS;
        for (int e = tid; e < nIn; e += 256) {
            int ic  = e / (TS * TS);
            int rem = e % (TS * TS);
            int yy  = rem / TS, xx = rem % TS;
            int gy = y0 + yy - 1, gx = x0 + xx - 1;
            float v = 0.f;
            if (gy >= 0 && gy < Hn && gx >= 0 && gx < Wn) {
                int c = ic0c + ic;
                if (c < ic_split) {
                    v = in0[((b * ic_split + c) * Hn + gy) * Wn + gx];
                } else {
                    v = in1[((b * ic1 + (c - ic_split)) * Hn + gy) * Wn + gx];
                }
            }
            s_in[ic][yy][xx] = v;
        }
        // ---- load weight chunk: s_w[ic][tap][oc] ----
        const int nW = OCT * ICB * 9;
        for (int e = tid; e < nW; e += 256) {
            int o   = e / (ICB * 9);
            int rem = e % (ICB * 9);
            int ic  = rem / 9, t = rem % 9;
            s_w[ic][t][o] = wgt[((oc0 + o) * IC + ic0c + ic) * 9 + t];
        }
        __syncthreads();

        // ---- compute ----
        #pragma unroll
        for (int ic = 0; ic < ICB; ic++) {
            #pragma unroll
            for (int t = 0; t < 9; t++) {
                const int ky = t / 3, kx = t % 3;
                float wv[OCT];
                #pragma unroll
                for (int o = 0; o < OCT; o++) wv[o] = s_w[ic][t][o];
                float iv[TPT][TPT];
                #pragma unroll
                for (int py = 0; py < TPT; py++)
                    #pragma unroll
                    for (int px = 0; px < TPT; px++)
                        iv[py][px] = s_in[ic][ty * TPT + py + ky][tx * TPT + px + kx];
                #pragma unroll
                for (int o = 0; o < OCT; o++)
                    #pragma unroll
                    for (int py = 0; py < TPT; py++)
                        #pragma unroll
                        for (int px = 0; px < TPT; px++)
                            acc[o][py][px] = fmaf(iv[py][px], wv[o], acc[o][py][px]);
            }
        }
        __syncthreads();
    }

    // ---- epilogue ----
    #pragma unroll
    for (int o = 0; o < OCT; o++) {
        float bv = bias[oc0 + o];
        #pragma unroll
        for (int py = 0; py < TPT; py++)
            #pragma unroll
            for (int px = 0; px < TPT; px++) {
                float v = acc[o][py][px] + bv;
                if (RELU) v = fmaxf(v, 0.f);
                int gy = y0 + ty * TPT + py;
                int gx = x0 + tx * TPT + px;
                out[((b * OC + oc0 + o) * Hn + gy) * Wn + gx] = v;
            }
    }
}

// ---------------------------------------------------------------------------
// Bilinear gather: materialize val[b][c*9+k][h][w] = bilinear(hr[b][c], p(k,h,w))
// with torchvision DeformConv v1 semantics (zero pad, per-corner validity).
// blockDim = (96, 3); grid = (96 h, 3 kgroups, 4 b).
// ---------------------------------------------------------------------------
__global__ void __launch_bounds__(288)
gather_k(const float* __restrict__ hr, const float* __restrict__ off)
{
    const int w = threadIdx.x;                        // 0..95
    const int k = blockIdx.y * 3 + threadIdx.y;       // 0..8
    const int h = blockIdx.x;
    const int b = blockIdx.z;
    const int ky = k / 3 - 1, kx = k % 3 - 1;

    const int oidx = ((b * 18 + 2 * k) * Hn + h) * Wn + w;
    const float dy = off[oidx];
    const float dx = off[oidx + HWn];
    const float py = (float)(h + ky) + dy;
    const float px = (float)(w + kx) + dx;
    const float y0f = floorf(py), x0f = floorf(px);
    const float ly = py - y0f, lx = px - x0f;
    const int y0 = (int)y0f, x0 = (int)x0f;
    const int y1 = y0 + 1, x1 = x0 + 1;

    const bool vy0 = (y0 >= 0) & (y0 < Hn);
    const bool vy1 = (y1 >= 0) & (y1 < Hn);
    const bool vx0 = (x0 >= 0) & (x0 < Wn);
    const bool vx1 = (x1 >= 0) & (x1 < Wn);

    const float w00 = (1.f - ly) * (1.f - lx) * (float)(vy0 & vx0);
    const float w01 = (1.f - ly) * lx        * (float)(vy0 & vx1);
    const float w10 = ly * (1.f - lx)        * (float)(vy1 & vx0);
    const float w11 = ly * lx                * (float)(vy1 & vx1);

    const int yc0 = min(max(y0, 0), Hn - 1), yc1 = min(max(y1, 0), Hn - 1);
    const int xc0 = min(max(x0, 0), Wn - 1), xc1 = min(max(x1, 0), Wn - 1);
    const int i00 = yc0 * Wn + xc0, i01 = yc0 * Wn + xc1;
    const int i10 = yc1 * Wn + xc0, i11 = yc1 * Wn + xc1;

    const float* base = hr + (size_t)b * Cn * HWn;
    float* dst = g_val + ((size_t)b * Rn + k) * HWn + h * Wn + w;

    #pragma unroll 4
    for (int c = 0; c < Cn; c++) {
        const float* p = base + c * HWn;
        float v = w00 * p[i00] + w01 * p[i01] + w10 * p[i10] + w11 * p[i11];
        dst[(size_t)c * 9 * HWn] = v;
    }
}

// ---------------------------------------------------------------------------
// 1x1 "conv" GEMM over R = C*9 reduction dim: out[b][o][h][w] =
//   sum_r w[o][r] * val[b][r][h][w] + bias[o]
// Tile 32x32 px, OCT oc per block, 2x2 px per thread.
// ---------------------------------------------------------------------------
template<int R_, int OC, int OCT, int ICB>
__global__ void __launch_bounds__(256)
gemm1x1_k(const float* __restrict__ in, const float* __restrict__ wgt,
          const float* __restrict__ bias, float* __restrict__ out)
{
    constexpr int TILE = 32, TPT = 2, TD = 16;
    constexpr int SS = 33;  // odd row stride

    __shared__ float s_in[ICB][TILE][SS];
    __shared__ float s_w[ICB][OCT];

    const int tx = threadIdx.x, ty = threadIdx.y;
    const int tid = ty * TD + tx;
    constexpr int nOC = OC / OCT;
    const int b   = blockIdx.z / nOC;
    const int oc0 = (blockIdx.z % nOC) * OCT;
    const int x0  = blockIdx.x * TILE;
    const int y0  = blockIdx.y * TILE;

    float acc[OCT][TPT][TPT];
    #pragma unroll
    for (int o = 0; o < OCT; o++)
        #pragma unroll
        for (int py = 0; py < TPT; py++)
            #pragma unroll
            for (int px = 0; px < TPT; px++)
                acc[o][py][px] = 0.f;

    for (int r0 = 0; r0 < R_; r0 += ICB) {
        const int nIn = ICB * TILE * TILE;
        for (int e = tid; e < nIn; e += 256) {
            int r   = e / (TILE * TILE);
            int rem = e % (TILE * TILE);
            int yy  = rem / TILE, xx = rem % TILE;
            s_in[r][yy][xx] =
                in[((size_t)(b * R_ + r0 + r)) * HWn + (y0 + yy) * Wn + x0 + xx];
        }
        const int nW = ICB * OCT;
        for (int e = tid; e < nW; e += 256) {
            int r = e / OCT, o = e % OCT;
            s_w[r][o] = wgt[(oc0 + o) * R_ + r0 + r];
        }
        __syncthreads();

        #pragma unroll
        for (int r = 0; r < ICB; r++) {
            float wv[OCT];
            #pragma unroll
            for (int o = 0; o < OCT; o++) wv[o] = s_w[r][o];
            float iv[TPT][TPT];
            #pragma unroll
            for (int py = 0; py < TPT; py++)
                #pragma unroll
                for (int px = 0; px < TPT; px++)
                    iv[py][px] = s_in[r][ty * TPT + py][tx * TPT + px];
            #pragma unroll
            for (int o = 0; o < OCT; o++)
                #pragma unroll
                for (int py = 0; py < TPT; py++)
                    #pragma unroll
                    for (int px = 0; px < TPT; px++)
                        acc[o][py][px] = fmaf(iv[py][px], wv[o], acc[o][py][px]);
        }
        __syncthreads();
    }

    #pragma unroll
    for (int o = 0; o < OCT; o++) {
        float bv = bias[oc0 + o];
        #pragma unroll
        for (int py = 0; py < TPT; py++)
            #pragma unroll
            for (int px = 0; px < TPT; px++) {
                int gy = y0 + ty * TPT + py;
                int gx = x0 + tx * TPT + px;
                out[((b * OC + oc0 + o) * Hn + gy) * Wn + gx] = acc[o][py][px] + bv;
            }
    }
}

// ---------------------------------------------------------------------------

extern "C" void kernel_launch(void* const* d_in, const int* in_sizes, int n_in,
                              void* d_out, int out_size)
{
    const float* lr    = (const float*)d_in[0];
    const float* hr    = (const float*)d_in[1];
    const float* est_w = (const float*)d_in[2];
    const float* est_b = (const float*)d_in[3];
    const float* off_w = (const float*)d_in[4];
    const float* off_b = (const float*)d_in[5];
    const float* dc_w  = (const float*)d_in[6];
    const float* dc_b  = (const float*)d_in[7];
    float* out = (float*)d_out;

    float *p_est, *p_off, *p_val;
    cudaGetSymbolAddress((void**)&p_est, g_est);
    cudaGetSymbolAddress((void**)&p_off, g_off);
    cudaGetSymbolAddress((void**)&p_val, g_val);

    dim3 blk(16, 16);

    // 1) est = relu(conv3x3(concat(lr,hr))): IC=256, OC=256
    {
        dim3 grid(Hn / 32, Wn / 32, Bn * (256 / 16));
        conv3x3_k<256, 256, 16, 16, 32, 2, 8, true>
            <<<grid, blk>>>(lr, hr, 128, est_w, est_b, p_est);
    }
    // 2) offset = conv3x3(est): IC=256, OC=18
    {
        dim3 grid(Hn / 16, Wn / 16, Bn * 1);
        conv3x3_k<256, 18, 18, 20, 16, 1, 8, false>
            <<<grid, blk>>>(p_est, p_est, 256, off_w, off_b, p_off);
    }
    // 3) bilinear gather -> g_val
    {
        dim3 grid(Hn, 3, Bn);
        dim3 b3(Wn, 3);
        gather_k<<<grid, b3>>>(hr, p_off);
    }
    // 4) deform weight contraction: out = W[128,1152] x val + bias
    {
        dim3 grid(Hn / 32, Wn / 32, Bn * (128 / 16));
        gemm1x1_k<Rn, 128, 16, 8><<<grid, blk>>>(p_val, dc_w, dc_b, out);
    }
}

// round 3
// speedup vs baseline: 1.6983x; 1.6983x over previous
#include <cuda_runtime.h>
#include <cstdint>

#define Bn 4
#define Cn 128
#define Hn 96
#define Wn 96
#define HWn (Hn*Wn)
#define Rn (Cn*9)

// Scratch (no allocations allowed).
__device__ float g_est[Bn*256*HWn];                 // 37.7 MB
__device__ float g_off[Bn*18*HWn];                  // 2.65 MB
__device__ float g_val[(size_t)Bn*Rn*HWn];          // 170 MB

// ---------------------------------------------------------------------------
__device__ __forceinline__ uint32_t smem_u32(const void* p) {
    return (uint32_t)__cvta_generic_to_shared(p);
}
__device__ __forceinline__ void cp_async4(uint32_t dst, const void* src, int src_sz) {
    asm volatile("cp.async.ca.shared.global [%0], [%1], 4, %2;"
                 :: "r"(dst), "l"(src), "r"(src_sz));
}
__device__ __forceinline__ void cp_commit() {
    asm volatile("cp.async.commit_group;" ::: "memory");
}
__device__ __forceinline__ void cp_wait0() {
    asm volatile("cp.async.wait_group 0;" ::: "memory");
}

// ---------------------------------------------------------------------------
// Generic 3x3 conv, NCHW, pad=1, stride=1, optional channel-concat input.
// 2-stage cp.async pipeline over ICB-channel chunks.
// ---------------------------------------------------------------------------
template<int IC, int OC, int OCT, int OCTP, int TILE, int TPT, int ICB, bool RELU>
__global__ void __launch_bounds__(256, 2)
conv3x3_k(const float* __restrict__ in0, const float* __restrict__ in1, int ic_split,
          const float* __restrict__ wgt, const float* __restrict__ bias,
          float* __restrict__ out)
{
    constexpr int TD = TILE / TPT;
    constexpr int TS = TILE + 2;
    constexpr int SS = (TS | 1);          // odd stride -> conflict-free

    __shared__ float s_in[2][ICB][TS][SS];
    __shared__ float s_w[2][ICB][9][OCTP];

    const int tx = threadIdx.x, ty = threadIdx.y;
    const int tid = ty * TD + tx;
    constexpr int nOC = OC / OCT;
    const int b   = blockIdx.z / nOC;
    const int oc0 = (blockIdx.z % nOC) * OCT;
    const int x0  = blockIdx.x * TILE;
    const int y0  = blockIdx.y * TILE;

    const int ic1 = IC - ic_split;

    float acc[OCT][TPT][TPT];
    #pragma unroll
    for (int o = 0; o < OCT; o++)
        #pragma unroll
        for (int py = 0; py < TPT; py++)
            #pragma unroll
            for (int px = 0; px < TPT; px++)
                acc[o][py][px] = 0.f;

    auto load_chunk = [&](int ic0c, int st) {
        const int nIn = ICB * TS * TS;
        for (int e = tid; e < nIn; e += 256) {
            int ic  = e / (TS * TS);
            int rem = e % (TS * TS);
            int yy  = rem / TS, xx = rem % TS;
            int gy = y0 + yy - 1, gx = x0 + xx - 1;
            bool ok = (gy >= 0) && (gy < Hn) && (gx >= 0) && (gx < Wn);
            int cgy = ok ? gy : 0, cgx = ok ? gx : 0;
            int c = ic0c + ic;
            const float* src;
            if (c < ic_split)
                src = in0 + ((size_t)(b * ic_split + c) * Hn + cgy) * Wn + cgx;
            else
                src = in1 + ((size_t)(b * ic1 + (c - ic_split)) * Hn + cgy) * Wn + cgx;
            cp_async4(smem_u32(&s_in[st][ic][yy][xx]), src, ok ? 4 : 0);
        }
        const int nW = OCT * ICB * 9;
        for (int e = tid; e < nW; e += 256) {
            int o   = e / (ICB * 9);
            int rem = e % (ICB * 9);
            int ic  = rem / 9, t = rem % 9;
            cp_async4(smem_u32(&s_w[st][ic][t][o]),
                      wgt + ((size_t)(oc0 + o) * IC + ic0c + ic) * 9 + t, 4);
        }
        cp_commit();
    };

    constexpr int NCH = IC / ICB;
    load_chunk(0, 0);

    for (int ch = 0; ch < NCH; ch++) {
        cp_wait0();
        __syncthreads();
        if (ch + 1 < NCH) load_chunk((ch + 1) * ICB, (ch + 1) & 1);
        const int st = ch & 1;

        #pragma unroll
        for (int ic = 0; ic < ICB; ic++) {
            #pragma unroll
            for (int t = 0; t < 9; t++) {
                const int ky = t / 3, kx = t % 3;
                float wv[OCT];
                #pragma unroll
                for (int o = 0; o < OCT; o++) wv[o] = s_w[st][ic][t][o];
                float iv[TPT][TPT];
                #pragma unroll
                for (int py = 0; py < TPT; py++)
                    #pragma unroll
                    for (int px = 0; px < TPT; px++)
                        iv[py][px] = s_in[st][ic][ty * TPT + py + ky][tx * TPT + px + kx];
                #pragma unroll
                for (int o = 0; o < OCT; o++)
                    #pragma unroll
                    for (int py = 0; py < TPT; py++)
                        #pragma unroll
                        for (int px = 0; px < TPT; px++)
                            acc[o][py][px] = fmaf(iv[py][px], wv[o], acc[o][py][px]);
            }
        }
        __syncthreads();
    }

    #pragma unroll
    for (int o = 0; o < OCT; o++) {
        float bv = bias[oc0 + o];
        #pragma unroll
        for (int py = 0; py < TPT; py++)
            #pragma unroll
            for (int px = 0; px < TPT; px++) {
                float v = acc[o][py][px] + bv;
                if (RELU) v = fmaxf(v, 0.f);
                int gy = y0 + ty * TPT + py;
                int gx = x0 + tx * TPT + px;
                out[((size_t)(b * OC + oc0 + o) * Hn + gy) * Wn + gx] = v;
            }
    }
}

// ---------------------------------------------------------------------------
// Bilinear gather: val[b][c*9+k][h][w] = bilinear(hr[b][c], p(k,h,w)).
// ---------------------------------------------------------------------------
__global__ void __launch_bounds__(288)
gather_k(const float* __restrict__ hr, const float* __restrict__ off)
{
    const int w = threadIdx.x;
    const int k = blockIdx.y * 3 + threadIdx.y;
    const int h = blockIdx.x;
    const int b = blockIdx.z;
    const int ky = k / 3 - 1, kx = k % 3 - 1;

    const int oidx = ((b * 18 + 2 * k) * Hn + h) * Wn + w;
    const float dy = off[oidx];
    const float dx = off[oidx + HWn];
    const float py = (float)(h + ky) + dy;
    const float px = (float)(w + kx) + dx;
    const float y0f = floorf(py), x0f = floorf(px);
    const float ly = py - y0f, lx = px - x0f;
    const int y0 = (int)y0f, x0 = (int)x0f;
    const int y1 = y0 + 1, x1 = x0 + 1;

    const bool vy0 = (y0 >= 0) & (y0 < Hn);
    const bool vy1 = (y1 >= 0) & (y1 < Hn);
    const bool vx0 = (x0 >= 0) & (x0 < Wn);
    const bool vx1 = (x1 >= 0) & (x1 < Wn);

    const float w00 = (1.f - ly) * (1.f - lx) * (float)(vy0 & vx0);
    const float w01 = (1.f - ly) * lx        * (float)(vy0 & vx1);
    const float w10 = ly * (1.f - lx)        * (float)(vy1 & vx0);
    const float w11 = ly * lx                * (float)(vy1 & vx1);

    const int yc0 = min(max(y0, 0), Hn - 1), yc1 = min(max(y1, 0), Hn - 1);
    const int xc0 = min(max(x0, 0), Wn - 1), xc1 = min(max(x1, 0), Wn - 1);
    const int i00 = yc0 * Wn + xc0, i01 = yc0 * Wn + xc1;
    const int i10 = yc1 * Wn + xc0, i11 = yc1 * Wn + xc1;

    const float* base = hr + (size_t)b * Cn * HWn;
    float* dst = g_val + ((size_t)b * Rn + k) * HWn + h * Wn + w;

    #pragma unroll 4
    for (int c = 0; c < Cn; c++) {
        const float* p = base + c * HWn;
        float v = w00 * p[i00] + w01 * p[i01] + w10 * p[i10] + w11 * p[i11];
        dst[(size_t)c * 9 * HWn] = v;
    }
}

// ---------------------------------------------------------------------------
// 1x1 GEMM over R = C*9 with 2-stage cp.async pipeline.
// ---------------------------------------------------------------------------
template<int R_, int OC, int OCT, int ICB>
__global__ void __launch_bounds__(256, 2)
gemm1x1_k(const float* __restrict__ in, const float* __restrict__ wgt,
          const float* __restrict__ bias, float* __restrict__ out)
{
    constexpr int TILE = 32, TPT = 2, TD = 16;
    constexpr int SS = 33;

    __shared__ float s_in[2][ICB][TILE][SS];
    __shared__ float s_w[2][ICB][OCT];

    const int tx = threadIdx.x, ty = threadIdx.y;
    const int tid = ty * TD + tx;
    constexpr int nOC = OC / OCT;
    const int b   = blockIdx.z / nOC;
    const int oc0 = (blockIdx.z % nOC) * OCT;
    const int x0  = blockIdx.x * TILE;
    const int y0  = blockIdx.y * TILE;

    float acc[OCT][TPT][TPT];
    #pragma unroll
    for (int o = 0; o < OCT; o++)
        #pragma unroll
        for (int py = 0; py < TPT; py++)
            #pragma unroll
            for (int px = 0; px < TPT; px++)
                acc[o][py][px] = 0.f;

    auto load_chunk = [&](int r0, int st) {
        const int nIn = ICB * TILE * TILE;
        for (int e = tid; e < nIn; e += 256) {
            int r   = e / (TILE * TILE);
            int rem = e % (TILE * TILE);
            int yy  = rem / TILE, xx = rem % TILE;
            cp_async4(smem_u32(&s_in[st][r][yy][xx]),
                      in + ((size_t)(b * R_ + r0 + r)) * HWn + (y0 + yy) * Wn + x0 + xx, 4);
        }
        const int nW = ICB * OCT;
        for (int e = tid; e < nW; e += 256) {
            int r = e / OCT, o = e % OCT;
            cp_async4(smem_u32(&s_w[st][r][o]), wgt + (size_t)(oc0 + o) * R_ + r0 + r, 4);
        }
        cp_commit();
    };

    constexpr int NCH = R_ / ICB;
    load_chunk(0, 0);

    for (int ch = 0; ch < NCH; ch++) {
        cp_wait0();
        __syncthreads();
        if (ch + 1 < NCH) load_chunk((ch + 1) * ICB, (ch + 1) & 1);
        const int st = ch & 1;

        #pragma unroll
        for (int r = 0; r < ICB; r++) {
            float wv[OCT];
            #pragma unroll
            for (int o = 0; o < OCT; o++) wv[o] = s_w[st][r][o];
            float iv[TPT][TPT];
            #pragma unroll
            for (int py = 0; py < TPT; py++)
                #pragma unroll
                for (int px = 0; px < TPT; px++)
                    iv[py][px] = s_in[st][r][ty * TPT + py][tx * TPT + px];
            #pragma unroll
            for (int o = 0; o < OCT; o++)
                #pragma unroll
                for (int py = 0; py < TPT; py++)
                    #pragma unroll
                    for (int px = 0; px < TPT; px++)
                        acc[o][py][px] = fmaf(iv[py][px], wv[o], acc[o][py][px]);
        }
        __syncthreads();
    }

    #pragma unroll
    for (int o = 0; o < OCT; o++) {
        float bv = bias[oc0 + o];
        #pragma unroll
        for (int py = 0; py < TPT; py++)
            #pragma unroll
            for (int px = 0; px < TPT; px++) {
                int gy = y0 + ty * TPT + py;
                int gx = x0 + tx * TPT + px;
                out[((size_t)(b * OC + oc0 + o) * Hn + gy) * Wn + gx] = acc[o][py][px] + bv;
            }
    }
}

// ---------------------------------------------------------------------------

extern "C" void kernel_launch(void* const* d_in, const int* in_sizes, int n_in,
                              void* d_out, int out_size)
{
    const float* lr    = (const float*)d_in[0];
    const float* hr    = (const float*)d_in[1];
    const float* est_w = (const float*)d_in[2];
    const float* est_b = (const float*)d_in[3];
    const float* off_w = (const float*)d_in[4];
    const float* off_b = (const float*)d_in[5];
    const float* dc_w  = (const float*)d_in[6];
    const float* dc_b  = (const float*)d_in[7];
    float* out = (float*)d_out;

    float *p_est, *p_off, *p_val;
    cudaGetSymbolAddress((void**)&p_est, g_est);
    cudaGetSymbolAddress((void**)&p_off, g_off);
    cudaGetSymbolAddress((void**)&p_val, g_val);

    dim3 blk(16, 16);

    // 1) est = relu(conv3x3(concat(lr,hr))): IC=256, OC=256
    {
        dim3 grid(Hn / 32, Wn / 32, Bn * (256 / 16));
        conv3x3_k<256, 256, 16, 16, 32, 2, 4, true>
            <<<grid, blk>>>(lr, hr, 128, est_w, est_b, p_est);
    }
    // 2) offset = conv3x3(est): IC=256, OC=18
    {
        dim3 grid(Hn / 16, Wn / 16, Bn * 1);
        conv3x3_k<256, 18, 18, 20, 16, 1, 4, false>
            <<<grid, blk>>>(p_est, p_est, 256, off_w, off_b, p_off);
    }
    // 3) bilinear gather -> g_val
    {
        dim3 grid(Hn, 3, Bn);
        dim3 b3(Wn, 3);
        gather_k<<<grid, b3>>>(hr, p_off);
    }
    // 4) deform weight contraction: out = W[128,1152] x val + bias
    {
        dim3 grid(Hn / 32, Wn / 32, Bn * (128 / 16));
        gemm1x1_k<Rn, 128, 16, 4><<<grid, blk>>>(p_val, dc_w, dc_b, out);
    }
}

// round 4
// speedup vs baseline: 1.8388x; 1.0827x over previous
#include <cuda_runtime.h>
#include <cstdint>

#define Bn 4
#define Cn 128
#define Hn 96
#define Wn 96
#define HWn (Hn*Wn)
#define Rn (Cn*9)

// Scratch (no allocations allowed).
__device__ float g_est[Bn*256*HWn];                 // 37.7 MB
__device__ float g_off[Bn*18*HWn];                  // 2.65 MB
__device__ float g_val[(size_t)Bn*Rn*HWn];          // 170 MB

// ---------------------------------------------------------------------------
__device__ __forceinline__ uint32_t smem_u32(const void* p) {
    return (uint32_t)__cvta_generic_to_shared(p);
}
__device__ __forceinline__ void cp_async4(uint32_t dst, const void* src, int src_sz) {
    asm volatile("cp.async.ca.shared.global [%0], [%1], 4, %2;"
                 :: "r"(dst), "l"(src), "r"(src_sz));
}
__device__ __forceinline__ void cp_async16(uint32_t dst, const void* src) {
    asm volatile("cp.async.cg.shared.global [%0], [%1], 16;"
                 :: "r"(dst), "l"(src));
}
__device__ __forceinline__ void cp_commit() {
    asm volatile("cp.async.commit_group;" ::: "memory");
}
__device__ __forceinline__ void cp_wait0() {
    asm volatile("cp.async.wait_group 0;" ::: "memory");
}

// ---- packed f32x2 (Blackwell FFMA2 path; ptxas never emits it from C++) ----
typedef unsigned long long u64;
__device__ __forceinline__ u64 pack2dup(float v) {
    u64 r;
    asm("mov.b64 %0, {%1,%1};" : "=l"(r) : "r"(__float_as_uint(v)));
    return r;
}
__device__ __forceinline__ void unpack2(u64 v, float& lo, float& hi) {
    unsigned a, b;
    asm("mov.b64 {%0,%1}, %2;" : "=r"(a), "=r"(b) : "l"(v));
    lo = __uint_as_float(a); hi = __uint_as_float(b);
}
__device__ __forceinline__ u64 fma2(u64 a, u64 b, u64 c) {
    u64 d;
    asm("fma.rn.f32x2 %0, %1, %2, %3;" : "=l"(d) : "l"(a), "l"(b), "l"(c));
    return d;
}

// ---------------------------------------------------------------------------
// 3x3 conv, NCHW, pad=1, stride=1, optional channel-concat input.
// 32x32 spatial tile, blockDim (8,32): thread = 4 contiguous px (x) * OCT oc.
// f32x2 packed math over oc-pairs. 2-stage cp.async pipeline over ICB chunks.
// ---------------------------------------------------------------------------
template<int IC, int OC, int OCT, int ICB, bool RELU>
__global__ void __launch_bounds__(256, 2)
conv3x3_k(const float* __restrict__ in0, const float* __restrict__ in1, int ic_split,
          const float* __restrict__ wgt, const float* __restrict__ bias,
          float* __restrict__ out)
{
    constexpr int OP = OCT / 2;
    constexpr int TS = 34;                // 32 + halo
    constexpr int SS = 37;                // stride: (5*ty'+4*tx) mod 32 is a permutation

    __shared__ __align__(16) float s_in[2][ICB][TS][SS];
    __shared__ __align__(16) float s_w[2][ICB][9][OCT];

    const int tx = threadIdx.x;           // 0..7  -> x = 4*tx
    const int ty = threadIdx.y;           // 0..31 -> y row
    const int tid = ty * 8 + tx;
    constexpr int nOC = OC / OCT;
    const int b   = blockIdx.z / nOC;
    const int oc0 = (blockIdx.z % nOC) * OCT;
    const int x0  = blockIdx.x * 32;
    const int y0  = blockIdx.y * 32;
    const int ic1 = IC - ic_split;

    u64 acc[4][OP];
    #pragma unroll
    for (int px = 0; px < 4; px++)
        #pragma unroll
        for (int op = 0; op < OP; op++) acc[px][op] = 0ULL;

    auto load_chunk = [&](int ic0c, int st) {
        const int nIn = ICB * TS * TS;
        for (int e = tid; e < nIn; e += 256) {
            int ic  = e / (TS * TS);
            int rem = e % (TS * TS);
            int yy  = rem / TS, xx = rem % TS;
            int gy = y0 + yy - 1, gx = x0 + xx - 1;
            bool ok = (gy >= 0) && (gy < Hn) && (gx >= 0) && (gx < Wn);
            int cgy = ok ? gy : 0, cgx = ok ? gx : 0;
            int c = ic0c + ic;
            const float* src;
            if (c < ic_split)
                src = in0 + ((size_t)(b * ic_split + c) * Hn + cgy) * Wn + cgx;
            else
                src = in1 + ((size_t)(b * ic1 + (c - ic_split)) * Hn + cgy) * Wn + cgx;
            cp_async4(smem_u32(&s_in[st][ic][yy][xx]), src, ok ? 4 : 0);
        }
        const int nW = ICB * 9 * OCT;
        for (int e = tid; e < nW; e += 256) {
            int ic  = e / (9 * OCT);
            int rem = e % (9 * OCT);
            int t   = rem / OCT, o = rem % OCT;
            cp_async4(smem_u32(&s_w[st][ic][t][o]),
                      wgt + ((size_t)(oc0 + o) * IC + ic0c + ic) * 9 + t, 4);
        }
        cp_commit();
    };

    constexpr int NCH = IC / ICB;
    load_chunk(0, 0);

    for (int ch = 0; ch < NCH; ch++) {
        cp_wait0();
        __syncthreads();
        if (ch + 1 < NCH) load_chunk((ch + 1) * ICB, (ch + 1) & 1);
        const int st = ch & 1;

        #pragma unroll
        for (int ic = 0; ic < ICB; ic++) {
            // 3 haloed rows x 6 scalars; reused across all 9 taps x 4 px
            float iv[3][6];
            #pragma unroll
            for (int ky = 0; ky < 3; ky++)
                #pragma unroll
                for (int j = 0; j < 6; j++)
                    iv[ky][j] = s_in[st][ic][ty + ky][tx * 4 + j];

            #pragma unroll
            for (int t = 0; t < 9; t++) {
                const int ky = t / 3, kx = t % 3;
                u64 wp[OP];
                const u64* w64 = reinterpret_cast<const u64*>(&s_w[st][ic][t][0]);
                #pragma unroll
                for (int op = 0; op < OP; op++) wp[op] = w64[op];
                #pragma unroll
                for (int px = 0; px < 4; px++) {
                    u64 a = pack2dup(iv[ky][kx + px]);
                    #pragma unroll
                    for (int op = 0; op < OP; op++)
                        acc[px][op] = fma2(a, wp[op], acc[px][op]);
                }
            }
        }
        __syncthreads();
    }

    // epilogue
    const int gy = y0 + ty;
    const int gx = x0 + tx * 4;
    #pragma unroll
    for (int op = 0; op < OP; op++) {
        float lo[4], hi[4];
        #pragma unroll
        for (int px = 0; px < 4; px++) unpack2(acc[px][op], lo[px], hi[px]);
        float b0 = bias[oc0 + 2 * op], b1 = bias[oc0 + 2 * op + 1];
        float4 v0, v1;
        v0.x = lo[0] + b0; v0.y = lo[1] + b0; v0.z = lo[2] + b0; v0.w = lo[3] + b0;
        v1.x = hi[0] + b1; v1.y = hi[1] + b1; v1.z = hi[2] + b1; v1.w = hi[3] + b1;
        if (RELU) {
            v0.x = fmaxf(v0.x, 0.f); v0.y = fmaxf(v0.y, 0.f);
            v0.z = fmaxf(v0.z, 0.f); v0.w = fmaxf(v0.w, 0.f);
            v1.x = fmaxf(v1.x, 0.f); v1.y = fmaxf(v1.y, 0.f);
            v1.z = fmaxf(v1.z, 0.f); v1.w = fmaxf(v1.w, 0.f);
        }
        *reinterpret_cast<float4*>(
            out + ((size_t)(b * OC + oc0 + 2 * op) * Hn + gy) * Wn + gx) = v0;
        *reinterpret_cast<float4*>(
            out + ((size_t)(b * OC + oc0 + 2 * op + 1) * Hn + gy) * Wn + gx) = v1;
    }
}

// ---------------------------------------------------------------------------
// Bilinear gather: val[b][c*9+k][h][w] = bilinear(hr[b][c], p(k,h,w)).
// ---------------------------------------------------------------------------
__global__ void __launch_bounds__(288)
gather_k(const float* __restrict__ hr, const float* __restrict__ off)
{
    const int w = threadIdx.x;
    const int k = blockIdx.y * 3 + threadIdx.y;
    const int h = blockIdx.x;
    const int b = blockIdx.z;
    const int ky = k / 3 - 1, kx = k % 3 - 1;

    const int oidx = ((b * 18 + 2 * k) * Hn + h) * Wn + w;
    const float dy = off[oidx];
    const float dx = off[oidx + HWn];
    const float py = (float)(h + ky) + dy;
    const float px = (float)(w + kx) + dx;
    const float y0f = floorf(py), x0f = floorf(px);
    const float ly = py - y0f, lx = px - x0f;
    const int y0 = (int)y0f, x0 = (int)x0f;
    const int y1 = y0 + 1, x1 = x0 + 1;

    const bool vy0 = (y0 >= 0) & (y0 < Hn);
    const bool vy1 = (y1 >= 0) & (y1 < Hn);
    const bool vx0 = (x0 >= 0) & (x0 < Wn);
    const bool vx1 = (x1 >= 0) & (x1 < Wn);

    const float w00 = (1.f - ly) * (1.f - lx) * (float)(vy0 & vx0);
    const float w01 = (1.f - ly) * lx        * (float)(vy0 & vx1);
    const float w10 = ly * (1.f - lx)        * (float)(vy1 & vx0);
    const float w11 = ly * lx                * (float)(vy1 & vx1);

    const int yc0 = min(max(y0, 0), Hn - 1), yc1 = min(max(y1, 0), Hn - 1);
    const int xc0 = min(max(x0, 0), Wn - 1), xc1 = min(max(x1, 0), Wn - 1);
    const int i00 = yc0 * Wn + xc0, i01 = yc0 * Wn + xc1;
    const int i10 = yc1 * Wn + xc0, i11 = yc1 * Wn + xc1;

    const float* base = hr + (size_t)b * Cn * HWn;
    float* dst = g_val + ((size_t)b * Rn + k) * HWn + h * Wn + w;

    #pragma unroll 4
    for (int c = 0; c < Cn; c++) {
        const float* p = base + c * HWn;
        float v = w00 * p[i00] + w01 * p[i01] + w10 * p[i10] + w11 * p[i11];
        dst[(size_t)c * 9 * HWn] = v;
    }
}

// ---------------------------------------------------------------------------
// 1x1 GEMM over R = C*9. 32x32 px tile, thread = 4 px * OCT oc, f32x2 packed.
// ---------------------------------------------------------------------------
template<int R_, int OC, int OCT, int ICB>
__global__ void __launch_bounds__(256, 2)
gemm1x1_k(const float* __restrict__ in, const float* __restrict__ wgt,
          const float* __restrict__ bias, float* __restrict__ out)
{
    constexpr int OP = OCT / 2;

    __shared__ __align__(16) float s_in[2][ICB][32][32];
    __shared__ __align__(16) float s_w[2][ICB][OCT];

    const int tx = threadIdx.x;           // 0..7
    const int ty = threadIdx.y;           // 0..31
    const int tid = ty * 8 + tx;
    constexpr int nOC = OC / OCT;
    const int b   = blockIdx.z / nOC;
    const int oc0 = (blockIdx.z % nOC) * OCT;
    const int x0  = blockIdx.x * 32;
    const int y0  = blockIdx.y * 32;

    u64 acc[4][OP];
    #pragma unroll
    for (int px = 0; px < 4; px++)
        #pragma unroll
        for (int op = 0; op < OP; op++) acc[px][op] = 0ULL;

    auto load_chunk = [&](int r0, int st) {
        // ICB * 1024 floats as 16B cp.async (coalesced, aligned: x0 % 32 == 0)
        #pragma unroll
        for (int i = 0; i < ICB; i++) {
            int e   = tid + i * 256;
            int r   = e >> 8;
            int rem = e & 255;
            int yy  = rem >> 3, x4 = rem & 7;
            cp_async16(smem_u32(&s_in[st][r][yy][x4 * 4]),
                       in + ((size_t)(b * R_ + r0 + r)) * HWn + (y0 + yy) * Wn + x0 + x4 * 4);
        }
        if (tid < ICB * OCT) {
            int r = tid / OCT, o = tid % OCT;
            cp_async4(smem_u32(&s_w[st][r][o]), wgt + (size_t)(oc0 + o) * R_ + r0 + r, 4);
        }
        cp_commit();
    };

    constexpr int NCH = R_ / ICB;
    load_chunk(0, 0);

    for (int ch = 0; ch < NCH; ch++) {
        cp_wait0();
        __syncthreads();
        if (ch + 1 < NCH) load_chunk((ch + 1) * ICB, (ch + 1) & 1);
        const int st = ch & 1;

        #pragma unroll
        for (int r = 0; r < ICB; r++) {
            float4 f4 = *reinterpret_cast<const float4*>(&s_in[st][r][ty][tx * 4]);
            u64 a0 = pack2dup(f4.x), a1 = pack2dup(f4.y);
            u64 a2 = pack2dup(f4.z), a3 = pack2dup(f4.w);
            u64 wp[OP];
            const u64* w64 = reinterpret_cast<const u64*>(&s_w[st][r][0]);
            #pragma unroll
            for (int op = 0; op < OP; op++) wp[op] = w64[op];
            #pragma unroll
            for (int op = 0; op < OP; op++) {
                acc[0][op] = fma2(a0, wp[op], acc[0][op]);
                acc[1][op] = fma2(a1, wp[op], acc[1][op]);
                acc[2][op] = fma2(a2, wp[op], acc[2][op]);
                acc[3][op] = fma2(a3, wp[op], acc[3][op]);
            }
        }
        __syncthreads();
    }

    const int gy = y0 + ty;
    const int gx = x0 + tx * 4;
    #pragma unroll
    for (int op = 0; op < OP; op++) {
        float lo[4], hi[4];
        #pragma unroll
        for (int px = 0; px < 4; px++) unpack2(acc[px][op], lo[px], hi[px]);
        float b0 = bias[oc0 + 2 * op], b1 = bias[oc0 + 2 * op + 1];
        float4 v0, v1;
        v0.x = lo[0] + b0; v0.y = lo[1] + b0; v0.z = lo[2] + b0; v0.w = lo[3] + b0;
        v1.x = hi[0] + b1; v1.y = hi[1] + b1; v1.z = hi[2] + b1; v1.w = hi[3] + b1;
        *reinterpret_cast<float4*>(
            out + ((size_t)(b * OC + oc0 + 2 * op) * Hn + gy) * Wn + gx) = v0;
        *reinterpret_cast<float4*>(
            out + ((size_t)(b * OC + oc0 + 2 * op + 1) * Hn + gy) * Wn + gx) = v1;
    }
}

// ---------------------------------------------------------------------------

extern "C" void kernel_launch(void* const* d_in, const int* in_sizes, int n_in,
                              void* d_out, int out_size)
{
    const float* lr    = (const float*)d_in[0];
    const float* hr    = (const float*)d_in[1];
    const float* est_w = (const float*)d_in[2];
    const float* est_b = (const float*)d_in[3];
    const float* off_w = (const float*)d_in[4];
    const float* off_b = (const float*)d_in[5];
    const float* dc_w  = (const float*)d_in[6];
    const float* dc_b  = (const float*)d_in[7];
    float* out = (float*)d_out;

    float *p_est, *p_off, *p_val;
    cudaGetSymbolAddress((void**)&p_est, g_est);
    cudaGetSymbolAddress((void**)&p_off, g_off);
    cudaGetSymbolAddress((void**)&p_val, g_val);

    dim3 blk(8, 32);

    // 1) est = relu(conv3x3(concat(lr,hr))): IC=256, OC=256
    {
        dim3 grid(Hn / 32, Wn / 32, Bn * (256 / 16));
        conv3x3_k<256, 256, 16, 4, true>
            <<<grid, blk>>>(lr, hr, 128, est_w, est_b, p_est);
    }
    // 2) offset = conv3x3(est): IC=256, OC=18
    {
        dim3 grid(Hn / 32, Wn / 32, Bn);
        conv3x3_k<256, 18, 18, 4, false>
            <<<grid, blk>>>(p_est, p_est, 256, off_w, off_b, p_off);
    }
    // 3) bilinear gather -> g_val
    {
        dim3 grid(Hn, 3, Bn);
        dim3 b3(Wn, 3);
        gather_k<<<grid, b3>>>(hr, p_off);
    }
    // 4) deform weight contraction: out = W[128,1152] x val + bias
    {
        dim3 grid(Hn / 32, Wn / 32, Bn * (128 / 16));
        gemm1x1_k<Rn, 128, 16, 4><<<grid, blk>>>(p_val, dc_w, dc_b, out);
    }
}